// round 16
// baseline (speedup 1.0000x reference)
#include <cuda_runtime.h>
#include <cuda_fp16.h>
#include <cstdint>
#include <cstddef>

#define XROW 10242
#define BROWS 16384
#define KT 64
#define NT 161                     // ceil(10242/64)
#define NT_SPLIT 81                // K-half boundary (tiles): sk0=[0,81), sk1=[81,161)
#define KPAD (NT * KT)             // 10304
#define NW 112                     // 96 emb cols + 3 count cols + pad
#define MT 64
#define ASTRIDE 144                // 64 halves (128B) + 16B pad -> row stride 36 banks == 4 mod 32
#define BSTRIDE 144
#define A_BYTES (MT * ASTRIDE)     // 9216
#define B_BYTES (NW * BSTRIDE)     // 16128
#define CSTRIDE 113
#define SMEM_DYN (2 * A_BYTES + 3 * B_BYTES + 1024)   // 67840; x3 CTAs = 203.5KB <= 228KB

__device__ __half g_Wh[NW * KPAD];              // packed block-structured fp16 weights
__device__ float  g_part[2u * BROWS * NW];      // split-K partial C (58.7 MB)

// ---------------- helpers ----------------
__device__ __forceinline__ uint32_t smem_u32(const void* p) {
    uint32_t a;
    asm("{ .reg .u64 t; cvta.to.shared.u64 t, %1; cvt.u32.u64 %0, t; }" : "=r"(a) : "l"(p));
    return a;
}
__device__ __forceinline__ void cp16(uint32_t dst, const void* src) {
    asm volatile("cp.async.cg.shared.global [%0], [%1], 16;" :: "r"(dst), "l"(src) : "memory");
}
__device__ __forceinline__ int2 ldcs64(const int* p) {
    int2 v;
    asm volatile("ld.global.cs.v2.s32 {%0,%1}, [%2];" : "=r"(v.x), "=r"(v.y) : "l"(p));
    return v;
}
__device__ __forceinline__ void ldsm4(uint32_t* r, uint32_t a) {
    asm volatile("ldmatrix.sync.aligned.m8n8.x4.shared.b16 {%0,%1,%2,%3}, [%4];"
                 : "=r"(r[0]), "=r"(r[1]), "=r"(r[2]), "=r"(r[3]) : "r"(a));
}
__device__ __forceinline__ void ldsm2(uint32_t* r, uint32_t a) {
    asm volatile("ldmatrix.sync.aligned.m8n8.x2.shared.b16 {%0,%1}, [%2];"
                 : "=r"(r[0]), "=r"(r[1]) : "r"(a));
}
__device__ __forceinline__ void mma16816(float* c, const uint32_t* a, uint32_t b0, uint32_t b1) {
    asm volatile(
        "mma.sync.aligned.m16n8k16.row.col.f32.f16.f16.f32 "
        "{%0,%1,%2,%3}, {%4,%5,%6,%7}, {%8,%9}, {%0,%1,%2,%3};"
        : "+f"(c[0]), "+f"(c[1]), "+f"(c[2]), "+f"(c[3])
        : "r"(a[0]), "r"(a[1]), "r"(a[2]), "r"(a[3]), "r"(b0), "r"(b1));
}
__device__ __forceinline__ uint32_t pack_h2(int a, int b) {
    __half2 hh = __floats2half2_rn((float)a, (float)b);
    return *reinterpret_cast<uint32_t*>(&hh);
}

// ---------------- prep: pack W into [NW][KPAD] fp16 ----------------
// k=0: rate idx (zero row); [1,26): genre; [26,2212): director; [2212,10242): actor;
// [10242,KPAD): zero pad. Rows 96/97/98 = count indicator rows (1.0) per segment.
__global__ void prep_w_kernel(const float* __restrict__ Wg,
                              const float* __restrict__ Wd,
                              const float* __restrict__ Wa) {
    int idx = blockIdx.x * blockDim.x + threadIdx.x;
    if (idx >= NW * KPAD) return;
    int n = idx / KPAD;
    int k = idx - n * KPAD;
    float v = 0.0f;
    if (k >= 1 && k < 26) {
        if (n < 32)       v = Wg[n * 25 + (k - 1)];
        else if (n == 96) v = 1.0f;
    } else if (k >= 26 && k < 2212) {
        if (n >= 32 && n < 64) v = Wd[(n - 32) * 2186 + (k - 26)];
        else if (n == 97)      v = 1.0f;
    } else if (k >= 2212 && k < 10242) {
        if (n >= 64 && n < 96) v = Wa[(n - 64) * 8030 + (k - 2212)];
        else if (n == 98)      v = 1.0f;
    }
    g_Wh[idx] = __float2half_rn(v);
}

// ---------------- main GEMM kernel (split-K x2, occupancy 3) ----------------
__global__ void __launch_bounds__(256, 3)
mli_main_kernel(const int* __restrict__ x) {
    extern __shared__ char smem_raw[];
    const int tid  = threadIdx.x;
    const int wid  = tid >> 5;
    const int lane = tid & 31;
    const int gid  = lane >> 2;
    const int tid4 = lane & 3;
    const int wm   = wid >> 1;         // 0..3 : 16-row M slice
    const int wn   = wid & 1;          // 0..1 : 56-col N slice

    const int sk     = blockIdx.x & 1;
    const int m_base = (blockIdx.x >> 1) * MT;
    const int T0 = sk ? NT_SPLIT : 0;
    const int T1 = sk ? NT : NT_SPLIT;

    uint32_t sbase = smem_u32(smem_raw);
    uint32_t tb = (sbase + 1023u) & ~1023u;
    const uint32_t Abuf[2] = { tb, tb + A_BYTES };
    const uint32_t Bbuf[3] = { tb + 2u * A_BYTES,
                               tb + 2u * A_BYTES + B_BYTES,
                               tb + 2u * A_BYTES + 2u * B_BYTES };

    // A staging: warp w handles rows w, w+8, ..., w+56; lane l loads int2 at col 2l.
    const int* xbase = x + (size_t)(m_base + wid) * XROW + 2 * lane;
    const uint32_t a_dst = (uint32_t)(wid * ASTRIDE + lane * 4);

    uint32_t hreg[8];                  // packed half2 per staged row
    auto load_a = [&](int k0, bool tail) {
        if (!tail) {
#pragma unroll
            for (int p = 0; p < 8; ++p) {
                int2 v = ldcs64(xbase + (size_t)p * 8 * XROW + k0);
                hreg[p] = pack_h2(v.x, v.y);
            }
        } else {
            int c0 = k0 + 2 * lane;
#pragma unroll
            for (int p = 0; p < 8; ++p) {
                const int* src = xbase + (size_t)p * 8 * XROW + k0;
                int v0 = (c0     < XROW) ? src[0] : 0;
                int v1 = (c0 + 1 < XROW) ? src[1] : 0;
                hreg[p] = pack_h2(v0, v1);
            }
        }
    };
    auto sts_a = [&](int buf) {
#pragma unroll
        for (int p = 0; p < 8; ++p)
            asm volatile("st.shared.b32 [%0], %1;"
                         :: "r"(Abuf[buf] + a_dst + (uint32_t)(p * 8 * ASTRIDE)),
                            "r"(hreg[p]) : "memory");
    };
    auto cp_b = [&](int k0, int buf) {
#pragma unroll
        for (int i = 0; i < 4; ++i) {
            int c = tid + i * 256;
            if (c < 896) {                       // 112 rows x 8 chunks of 16B
                int n = c >> 3, ch = c & 7;
                cp16(Bbuf[buf] + (uint32_t)(n * BSTRIDE + ch * 16),
                     g_Wh + (size_t)n * KPAD + k0 + ch * 8);
            }
        }
        asm volatile("cp.async.commit_group;" ::: "memory");
    };

    // ldmatrix lane-address offsets
    const uint32_t a_off =
        (uint32_t)((wm * 16 + ((lane >> 3) & 1) * 8 + (lane & 7)) * ASTRIDE
                   + (lane >> 4) * 16);
    uint32_t b_off[3];
#pragma unroll
    for (int jp = 0; jp < 3; ++jp)
        b_off[jp] = (uint32_t)((wn * 56 + jp * 16 + (lane >> 4) * 8 + (lane & 7)) * BSTRIDE
                               + ((lane >> 3) & 1) * 16);
    const uint32_t b_off2 =
        (uint32_t)((wn * 56 + 48 + (lane & 7)) * BSTRIDE + ((lane >> 3) & 1) * 16);

    float acc[7][4];
#pragma unroll
    for (int j = 0; j < 7; ++j)
#pragma unroll
        for (int q = 0; q < 4; ++q) acc[j][q] = 0.0f;

    // ---- prologue: stage tiles T0 and T0+1 ----
    load_a(T0 * KT, false);
    cp_b(T0 * KT, T0 % 3);
    sts_a(T0 & 1);
    load_a((T0 + 1) * KT, false);
    cp_b((T0 + 1) * KT, (T0 + 1) % 3);

    for (int t = T0; t < T1; ++t) {
        if (t + 1 < T1) {
            asm volatile("cp.async.wait_group 1;" ::: "memory");
        } else {
            asm volatile("cp.async.wait_group 0;" ::: "memory");
        }
        __syncthreads();

        if (t + 1 < T1) sts_a((t + 1) & 1);
        if (t + 2 < T1) {
            load_a((t + 2) * KT, (t + 2) == NT - 1);
            cp_b((t + 2) * KT, (t + 2) % 3);
        }

        const uint32_t Ab = Abuf[t & 1], Bb = Bbuf[t % 3];
#pragma unroll
        for (int ks = 0; ks < 4; ++ks) {
            uint32_t afr[4];
            ldsm4(afr, Ab + a_off + ks * 32);
            uint32_t bfr[7][2];
#pragma unroll
            for (int jp = 0; jp < 3; ++jp) {
                uint32_t t4[4];
                ldsm4(t4, Bb + b_off[jp] + ks * 32);
                bfr[2 * jp][0] = t4[0]; bfr[2 * jp][1] = t4[1];
                bfr[2 * jp + 1][0] = t4[2]; bfr[2 * jp + 1][1] = t4[3];
            }
            ldsm2(bfr[6], Bb + b_off2 + ks * 32);
#pragma unroll
            for (int j = 0; j < 7; ++j)
                mma16816(acc[j], afr, bfr[j][0], bfr[j][1]);
        }
    }
    __syncthreads();   // protect C overlay of tile buffers

    // ---- stage C in SMEM, then coalesced dump to split-K scratch ----
    float* Cs = (float*)(smem_raw + (tb - sbase));
    {
        int r0 = wm * 16 + gid;
#pragma unroll
        for (int j = 0; j < 7; ++j) {
            int c0 = wn * 56 + j * 8 + tid4 * 2;
            Cs[r0 * CSTRIDE + c0]           = acc[j][0];
            Cs[r0 * CSTRIDE + c0 + 1]       = acc[j][1];
            Cs[(r0 + 8) * CSTRIDE + c0]     = acc[j][2];
            Cs[(r0 + 8) * CSTRIDE + c0 + 1] = acc[j][3];
        }
    }
    __syncthreads();

    float* dst = g_part + ((size_t)sk * BROWS + m_base) * NW;
    for (int i = tid; i < MT * NW; i += 256) {
        int row = i / NW, col = i - row * NW;
        dst[(size_t)row * NW + col] = Cs[row * CSTRIDE + col];
    }
}

// ---------------- combine: sum K-halves, epilogue, write out ----------------
__global__ void __launch_bounds__(256)
mli_combine_kernel(const int* __restrict__ x,
                   const float* __restrict__ rate_table,
                   float* __restrict__ out) {
    const int tid = threadIdx.x;
    const int row = tid >> 2;          // 0..63
    const int seg = tid & 3;           // 0: rate, 1: genre, 2: director, 3: actor
    const int rg  = blockIdx.x * 64 + row;
    const size_t H = (size_t)BROWS * NW;
    const float* p = g_part + (size_t)rg * NW;
    float4* o = (float4*)(out + (size_t)rg * 128);

    if (seg == 0) {
        int ridx = x[(size_t)rg * XROW];
        const float4* rt = (const float4*)(rate_table + ridx * 32);
        float4 rv[8];
        float sq = 0.0f;
#pragma unroll
        for (int i = 0; i < 8; ++i) {
            rv[i] = rt[i];
            sq += rv[i].x * rv[i].x + rv[i].y * rv[i].y
                + rv[i].z * rv[i].z + rv[i].w * rv[i].w;
        }
        float norm = sqrtf(sq);
        float scale = (norm > 1.0f) ? (1.0f / (norm + 1e-7f)) : 1.0f;
#pragma unroll
        for (int i = 0; i < 8; ++i)
            o[i] = make_float4(rv[i].x * scale, rv[i].y * scale,
                               rv[i].z * scale, rv[i].w * scale);
    } else {
        float inv = 1.0f / (p[95 + seg] + p[H + 95 + seg]);
        const float* s0 = p + (seg - 1) * 32;
#pragma unroll
        for (int i = 0; i < 8; ++i)
            o[seg * 8 + i] = make_float4((s0[4*i+0] + s0[H+4*i+0]) * inv,
                                         (s0[4*i+1] + s0[H+4*i+1]) * inv,
                                         (s0[4*i+2] + s0[H+4*i+2]) * inv,
                                         (s0[4*i+3] + s0[H+4*i+3]) * inv);
    }
}

// ---------------- launch ----------------
extern "C" void kernel_launch(void* const* d_in, const int* in_sizes, int n_in,
                              void* d_out, int out_size) {
    (void)in_sizes; (void)n_in; (void)out_size;
    const int*   x    = (const int*)d_in[0];
    const float* rate = (const float*)d_in[1];
    const float* Wg   = (const float*)d_in[2];
    const float* Wd   = (const float*)d_in[3];
    const float* Wa   = (const float*)d_in[4];
    float*       out  = (float*)d_out;

    prep_w_kernel<<<(NW * KPAD + 255) / 256, 256>>>(Wg, Wd, Wa);

    cudaFuncSetAttribute(mli_main_kernel,
                         cudaFuncAttributeMaxDynamicSharedMemorySize, SMEM_DYN);
    mli_main_kernel<<<(BROWS / MT) * 2, 256, SMEM_DYN>>>(x);

    mli_combine_kernel<<<BROWS / 64, 256>>>(x, rate, out);
}

// round 17
// speedup vs baseline: 1.4134x; 1.4134x over previous
#include <cuda_runtime.h>
#include <cuda_fp16.h>
#include <cstdint>
#include <cstddef>

#define XROW 10242
#define BROWS 16384
#define KT 64
#define NT 161                     // ceil(10242/64)
#define KPAD (NT * KT)             // 10304
#define NW 128                     // 96 emb + 3 count + zero pad to 128 (4-way N split)
#define MT 64
#define ASTRIDE 144                // 64 halves (128B) + 16B pad -> stride 36 banks == 4 mod 32
#define BSTRIDE 144
#define A_BYTES (MT * ASTRIDE)     // 9216
#define B_BYTES (NW * BSTRIDE)     // 18432
#define CSTRIDE 113
#define SMEM_DYN (2 * A_BYTES + 3 * B_BYTES + 1024)   // 74752; x2 CTAs = 149.5KB

__device__ __half g_Wh[NW * KPAD]; // packed block-structured fp16 weights (~2.6 MB)

// ---------------- helpers ----------------
__device__ __forceinline__ uint32_t smem_u32(const void* p) {
    uint32_t a;
    asm("{ .reg .u64 t; cvta.to.shared.u64 t, %1; cvt.u32.u64 %0, t; }" : "=r"(a) : "l"(p));
    return a;
}
__device__ __forceinline__ void cp16(uint32_t dst, const void* src) {
    asm volatile("cp.async.cg.shared.global [%0], [%1], 16;" :: "r"(dst), "l"(src) : "memory");
}
__device__ __forceinline__ int2 ldcs64(const int* p) {
    int2 v;
    asm volatile("ld.global.cs.v2.s32 {%0,%1}, [%2];" : "=r"(v.x), "=r"(v.y) : "l"(p));
    return v;
}
__device__ __forceinline__ void ldsm4(uint32_t* r, uint32_t a) {
    asm volatile("ldmatrix.sync.aligned.m8n8.x4.shared.b16 {%0,%1,%2,%3}, [%4];"
                 : "=r"(r[0]), "=r"(r[1]), "=r"(r[2]), "=r"(r[3]) : "r"(a));
}
__device__ __forceinline__ void mma16816(float* c, const uint32_t* a, uint32_t b0, uint32_t b1) {
    asm volatile(
        "mma.sync.aligned.m16n8k16.row.col.f32.f16.f16.f32 "
        "{%0,%1,%2,%3}, {%4,%5,%6,%7}, {%8,%9}, {%0,%1,%2,%3};"
        : "+f"(c[0]), "+f"(c[1]), "+f"(c[2]), "+f"(c[3])
        : "r"(a[0]), "r"(a[1]), "r"(a[2]), "r"(a[3]), "r"(b0), "r"(b1));
}
__device__ __forceinline__ uint32_t pack_h2(int a, int b) {
    __half2 hh = __floats2half2_rn((float)a, (float)b);
    return *reinterpret_cast<uint32_t*>(&hh);
}

// ---------------- prep: pack W into [NW][KPAD] fp16 ----------------
// k=0: rate idx (zero row); [1,26): genre; [26,2212): director; [2212,10242): actor;
// [10242,KPAD): zero pad. Rows 96/97/98 = count indicator rows; rows 99..127 zero.
__global__ void prep_w_kernel(const float* __restrict__ Wg,
                              const float* __restrict__ Wd,
                              const float* __restrict__ Wa) {
    int idx = blockIdx.x * blockDim.x + threadIdx.x;
    if (idx >= NW * KPAD) return;
    int n = idx / KPAD;
    int k = idx - n * KPAD;
    float v = 0.0f;
    if (k >= 1 && k < 26) {
        if (n < 32)       v = Wg[n * 25 + (k - 1)];
        else if (n == 96) v = 1.0f;
    } else if (k >= 26 && k < 2212) {
        if (n >= 32 && n < 64) v = Wd[(n - 32) * 2186 + (k - 26)];
        else if (n == 97)      v = 1.0f;
    } else if (k >= 2212 && k < 10242) {
        if (n >= 64 && n < 96) v = Wa[(n - 64) * 8030 + (k - 2212)];
        else if (n == 98)      v = 1.0f;
    }
    g_Wh[idx] = __float2half_rn(v);
}

// ---------------- main kernel: 512 threads, 16 warps (4M x 4N), occ 2 ----------------
__global__ void __launch_bounds__(512, 2)
mli_main_kernel(const int* __restrict__ x,
                const float* __restrict__ rate_table,
                float* __restrict__ out) {
    extern __shared__ char smem_raw[];
    const int tid  = threadIdx.x;
    const int wid  = tid >> 5;         // 0..15
    const int lane = tid & 31;
    const int gid  = lane >> 2;
    const int tid4 = lane & 3;
    const int wm   = wid >> 2;         // 0..3 : 16-row M slice
    const int wn   = wid & 3;          // 0..3 : 32-col N slice
    const int m_base = blockIdx.x * MT;

    uint32_t sbase = smem_u32(smem_raw);
    uint32_t tb = (sbase + 1023u) & ~1023u;
    const uint32_t Abuf[2] = { tb, tb + A_BYTES };
    const uint32_t Bbuf[3] = { tb + 2u * A_BYTES,
                               tb + 2u * A_BYTES + B_BYTES,
                               tb + 2u * A_BYTES + 2u * B_BYTES };

    // A staging: warp w handles rows w, w+16, w+32, w+48; lane l loads int2 at col 2l.
    const int* xbase = x + (size_t)(m_base + wid) * XROW + 2 * lane;
    const uint32_t a_dst = (uint32_t)(wid * ASTRIDE + lane * 4);

    uint32_t hreg[4];
    auto load_a = [&](int k0, bool tail) {
        if (!tail) {
#pragma unroll
            for (int p = 0; p < 4; ++p) {
                int2 v = ldcs64(xbase + (size_t)p * 16 * XROW + k0);
                hreg[p] = pack_h2(v.x, v.y);
            }
        } else {
            int c0 = k0 + 2 * lane;
#pragma unroll
            for (int p = 0; p < 4; ++p) {
                const int* src = xbase + (size_t)p * 16 * XROW + k0;
                int v0 = (c0     < XROW) ? src[0] : 0;
                int v1 = (c0 + 1 < XROW) ? src[1] : 0;
                hreg[p] = pack_h2(v0, v1);
            }
        }
    };
    auto sts_a = [&](int buf) {
#pragma unroll
        for (int p = 0; p < 4; ++p)
            asm volatile("st.shared.b32 [%0], %1;"
                         :: "r"(Abuf[buf] + a_dst + (uint32_t)(p * 16 * ASTRIDE)),
                            "r"(hreg[p]) : "memory");
    };
    auto cp_b = [&](int k0, int buf) {
#pragma unroll
        for (int i = 0; i < 2; ++i) {
            int c = tid + i * 512;               // 1024 = 128 rows x 8 chunks of 16B
            int n = c >> 3, ch = c & 7;
            cp16(Bbuf[buf] + (uint32_t)(n * BSTRIDE + ch * 16),
                 g_Wh + (size_t)n * KPAD + k0 + ch * 8);
        }
        asm volatile("cp.async.commit_group;" ::: "memory");
    };

    // ldmatrix lane-address offsets
    const uint32_t a_off =
        (uint32_t)((wm * 16 + ((lane >> 3) & 1) * 8 + (lane & 7)) * ASTRIDE
                   + (lane >> 4) * 16);
    uint32_t b_off[2];
#pragma unroll
    for (int jp = 0; jp < 2; ++jp)
        b_off[jp] = (uint32_t)((wn * 32 + jp * 16 + (lane >> 4) * 8 + (lane & 7)) * BSTRIDE
                               + ((lane >> 3) & 1) * 16);

    float acc[4][4];
#pragma unroll
    for (int j = 0; j < 4; ++j)
#pragma unroll
        for (int q = 0; q < 4; ++q) acc[j][q] = 0.0f;

    // ---- prologue: stage tiles 0 and 1 ----
    load_a(0, false);
    cp_b(0, 0);
    sts_a(0);
    load_a(KT, false);
    cp_b(KT, 1);

    // Invariant at iter t: groups committed for tiles <= t+1, A regs hold t+1,
    // Abuf[t&1] holds tile t.
    for (int t = 0; t < NT; ++t) {
        if (t + 1 < NT) {
            asm volatile("cp.async.wait_group 1;" ::: "memory");
        } else {
            asm volatile("cp.async.wait_group 0;" ::: "memory");
        }
        __syncthreads();

        if (t + 1 < NT) sts_a((t + 1) & 1);
        if (t + 2 < NT) {
            load_a((t + 2) * KT, (t + 2) == NT - 1);
            cp_b((t + 2) * KT, (t + 2) % 3);
        }

        const uint32_t Ab = Abuf[t & 1], Bb = Bbuf[t % 3];
#pragma unroll
        for (int ks = 0; ks < 4; ++ks) {
            uint32_t afr[4];
            ldsm4(afr, Ab + a_off + ks * 32);
#pragma unroll
            for (int jp = 0; jp < 2; ++jp) {
                uint32_t t4[4];
                ldsm4(t4, Bb + b_off[jp] + ks * 32);
                mma16816(acc[2 * jp],     afr, t4[0], t4[1]);
                mma16816(acc[2 * jp + 1], afr, t4[2], t4[3]);
            }
        }
    }
    __syncthreads();   // protect C overlay of tile buffers

    // ---------------- epilogue ----------------
    float* Cs = (float*)(smem_raw + (tb - sbase));
    {
        int r0 = wm * 16 + gid;
#pragma unroll
        for (int j = 0; j < 4; ++j) {
            int c0 = wn * 32 + j * 8 + tid4 * 2;
            if (c0 < 99) {
                Cs[r0 * CSTRIDE + c0]           = acc[j][0];
                Cs[r0 * CSTRIDE + c0 + 1]       = acc[j][1];
                Cs[(r0 + 8) * CSTRIDE + c0]     = acc[j][2];
                Cs[(r0 + 8) * CSTRIDE + c0 + 1] = acc[j][3];
            }
        }
    }
    __syncthreads();

    if (tid < 256) {
        const int row = tid >> 2;          // 0..63
        const int seg = tid & 3;           // 0: rate, 1: genre, 2: director, 3: actor
        const int rg  = m_base + row;
        const float* cr = Cs + row * CSTRIDE;
        float4* o = (float4*)(out + (size_t)rg * 128);

        if (seg == 0) {
            int ridx = x[(size_t)rg * XROW];
            const float4* rt = (const float4*)(rate_table + ridx * 32);
            float4 rv[8];
            float sq = 0.0f;
#pragma unroll
            for (int i = 0; i < 8; ++i) {
                rv[i] = rt[i];
                sq += rv[i].x * rv[i].x + rv[i].y * rv[i].y
                    + rv[i].z * rv[i].z + rv[i].w * rv[i].w;
            }
            float norm = sqrtf(sq);
            float scale = (norm > 1.0f) ? (1.0f / (norm + 1e-7f)) : 1.0f;
#pragma unroll
            for (int i = 0; i < 8; ++i)
                o[i] = make_float4(rv[i].x * scale, rv[i].y * scale,
                                   rv[i].z * scale, rv[i].w * scale);
        } else {
            float inv = 1.0f / cr[95 + seg];
            const float* src = cr + (seg - 1) * 32;
#pragma unroll
            for (int i = 0; i < 8; ++i)
                o[seg * 8 + i] = make_float4(src[4 * i + 0] * inv, src[4 * i + 1] * inv,
                                             src[4 * i + 2] * inv, src[4 * i + 3] * inv);
        }
    }
}

// ---------------- launch ----------------
extern "C" void kernel_launch(void* const* d_in, const int* in_sizes, int n_in,
                              void* d_out, int out_size) {
    (void)in_sizes; (void)n_in; (void)out_size;
    const int*   x    = (const int*)d_in[0];
    const float* rate = (const float*)d_in[1];
    const float* Wg   = (const float*)d_in[2];
    const float* Wd   = (const float*)d_in[3];
    const float* Wa   = (const float*)d_in[4];
    float*       out  = (float*)d_out;

    prep_w_kernel<<<(NW * KPAD + 255) / 256, 256>>>(Wg, Wd, Wa);

    cudaFuncSetAttribute(mli_main_kernel,
                         cudaFuncAttributeMaxDynamicSharedMemorySize, SMEM_DYN);
    mli_main_kernel<<<BROWS / MT, 512, SMEM_DYN>>>(x, rate, out);
}